// round 1
// baseline (speedup 1.0000x reference)
#include <cuda_runtime.h>
#include <cuda_bf16.h>
#include <math.h>

// PMSN / S4D kernel:
//   A      = -exp(log_A_real) + i*A_imag                  (H,N)
//   dt     = exp(log_dt)                                  (H,)
//   Adt    = A*dt ; A_bar = exp(Adt)
//   B_bar  = (A_bar - 1) * B / A
//   out[h,l] = Re( sum_n (C*B_bar)_n * exp(Adt_n * l) )   (H,L)
//
// Strategy: one block per h. Thread t owns l = 2t, 2t+1 (float2 store),
// advancing by stride = 2*blockDim with a complex multiply by
// w = A_bar^stride. Seed phase computed once per thread with
// double-precision mod-2pi reduction + small-argument sincosf.

#define NSTATE 4

__device__ __forceinline__ void phase_sincos(double theta, float* s, float* c) {
    const double TWO_PI     = 6.283185307179586476925287;
    const double INV_TWO_PI = 0.15915494309189533576888;
    double k = rint(theta * INV_TWO_PI);
    float r = (float)(theta - k * TWO_PI);   // |r| <= pi -> fast accurate path
    sincosf(r, s, c);
}

__global__ __launch_bounds__(256, 4)
void pmsn_kernel(const float* __restrict__ log_dt,
                 const float* __restrict__ log_A_real,
                 const float* __restrict__ A_imag,
                 const float* __restrict__ VinvB_real,
                 const float* __restrict__ VinvB_imag,
                 const float* __restrict__ CV_real,
                 const float* __restrict__ CV_imag,
                 float* __restrict__ out,
                 int L)
{
    const int h   = blockIdx.x;
    const int tid = threadIdx.x;
    const int stride = 2 * blockDim.x;   // l-advance per iteration
    const int l0  = 2 * tid;

    const float dt = expf(log_dt[h]);

    // Per-n state: z0 = value at l, z1 = value at l+1, w = step factor.
    float z0r[NSTATE], z0i[NSTATE], z1r[NSTATE], z1i[NSTATE];
    float wr[NSTATE],  wi[NSTATE];

#pragma unroll
    for (int n = 0; n < NSTATE; ++n) {
        const int idx = h * NSTATE + n;
        const float Are = -expf(log_A_real[idx]);
        const float Aim = A_imag[idx];
        const float a = Are * dt;           // Re(Adt)  (<= 0)
        const float b = Aim * dt;           // Im(Adt)

        // A_bar = exp(Adt)
        float sb, cb;
        sincosf(b, &sb, &cb);
        const float ea  = expf(a);
        const float Abr = ea * cb;
        const float Abi = ea * sb;

        // B_bar = (A_bar - 1) * B / A
        const float Br = VinvB_real[idx], Bi = VinvB_imag[idx];
        const float t1r = (Abr - 1.0f) * Br - Abi * Bi;
        const float t1i = (Abr - 1.0f) * Bi + Abi * Br;
        const float invA = 1.0f / (Are * Are + Aim * Aim);
        const float Bbr = (t1r * Are + t1i * Aim) * invA;
        const float Bbi = (t1i * Are - t1r * Aim) * invA;

        // coeff = C * B_bar
        const float Cr = CV_real[idx], Ci = CV_imag[idx];
        const float cr = Cr * Bbr - Ci * Bbi;
        const float ci = Cr * Bbi + Ci * Bbr;

        // z0 = coeff * exp(Adt * l0)  (accurate seed phase)
        float s0, c0;
        phase_sincos((double)b * (double)l0, &s0, &c0);
        const float m0 = expf(a * (float)l0);
        const float e0r = m0 * c0, e0i = m0 * s0;
        z0r[n] = cr * e0r - ci * e0i;
        z0i[n] = cr * e0i + ci * e0r;

        // z1 = z0 * A_bar  (value at l0+1)
        z1r[n] = z0r[n] * Abr - z0i[n] * Abi;
        z1i[n] = z0r[n] * Abi + z0i[n] * Abr;

        // w = A_bar^stride = exp(Adt * stride)
        float sw, cw;
        phase_sincos((double)b * (double)stride, &sw, &cw);
        const float mw = expf(a * (float)stride);
        wr[n] = mw * cw;
        wi[n] = mw * sw;
    }

    float* rowp = out + (size_t)h * (size_t)L;

    for (int l = l0; l < L; l += stride) {
        const float s0 = (z0r[0] + z0r[1]) + (z0r[2] + z0r[3]);
        const float s1 = (z1r[0] + z1r[1]) + (z1r[2] + z1r[3]);
        if (l + 1 < L) {
            *reinterpret_cast<float2*>(rowp + l) = make_float2(s0, s1);
        } else {
            rowp[l] = s0;
        }
#pragma unroll
        for (int n = 0; n < NSTATE; ++n) {
            const float a0r = z0r[n] * wr[n] - z0i[n] * wi[n];
            const float a0i = z0r[n] * wi[n] + z0i[n] * wr[n];
            const float a1r = z1r[n] * wr[n] - z1i[n] * wi[n];
            const float a1i = z1r[n] * wi[n] + z1i[n] * wr[n];
            z0r[n] = a0r; z0i[n] = a0i;
            z1r[n] = a1r; z1i[n] = a1i;
        }
    }
}

extern "C" void kernel_launch(void* const* d_in, const int* in_sizes, int n_in,
                              void* d_out, int out_size)
{
    const float* log_dt     = (const float*)d_in[0];
    const float* log_A_real = (const float*)d_in[1];
    const float* A_imag     = (const float*)d_in[2];
    const float* VinvB_real = (const float*)d_in[3];
    const float* VinvB_imag = (const float*)d_in[4];
    const float* CV_real    = (const float*)d_in[5];
    const float* CV_imag    = (const float*)d_in[6];
    // d_in[7] is L on device; derive L on host instead (graph-capture safe):
    const int H = in_sizes[0];
    const int L = out_size / H;

    float* out = (float*)d_out;

    dim3 grid(H);
    dim3 block(256);
    pmsn_kernel<<<grid, block>>>(log_dt, log_A_real, A_imag,
                                 VinvB_real, VinvB_imag,
                                 CV_real, CV_imag, out, L);
}

// round 2
// speedup vs baseline: 2.2898x; 2.2898x over previous
#include <cuda_runtime.h>
#include <cuda_bf16.h>
#include <math.h>

// PMSN / S4D:  out[h,l] = Re( sum_n coeff_{h,n} * A_bar_{h,n}^l ),
//   coeff = C * B_bar,  B_bar = (A_bar-1)*B/A,  A_bar = exp(A*dt).
//
// R2 strategy: kill the per-thread transcendental prologue.
//  - 32 setup lanes per block compute A_bar, coeff, powers A_bar^(4*2^k)
//    (k=0..6) and w = A_bar^512 into smem (fp32 Cody-Waite phase reduction;
//    scale factors are powers of two so b*m is exact).
//  - Each of 128 threads composes its seed A_bar^(4*tid) with <=7 complex
//    mults from smem broadcasts (FMA pipe only).
//  - Main loop: 4 l per thread (float4 store), stride 512, advance by w.

#define NSTATE 4
#define TPB    128
#define LPT    4            // l-values per thread
#define STRIDE (TPB * LPT)  // 512

struct __align__(8) cfloat { float r, i; };

__device__ __forceinline__ cfloat cmul(cfloat a, cfloat b) {
    cfloat o;
    o.r = fmaf(a.r, b.r, -a.i * b.i);
    o.i = fmaf(a.r, b.i,  a.i * b.r);
    return o;
}

// exp((a + i b) * m), m a (small) power of two -> b*m exact.
__device__ __forceinline__ cfloat cexp_scaled(float a, float b, float m) {
    const float INV2PI = 0.15915494309189535f;
    const float C1     = 6.28125f;                  // exact in fp32
    const float C2     = 1.9353071795864764e-3f;    // 2*pi - C1
    float am = a * m;
    float bm = b * m;
    float k  = rintf(bm * INV2PI);
    float r  = fmaf(-k, C1, bm);
    r        = fmaf(-k, C2, r);
    float s, c;
    sincosf(r, &s, &c);
    float e = expf(am);
    cfloat o; o.r = e * c; o.i = e * s;
    return o;
}

__global__ __launch_bounds__(TPB, 8)
void pmsn_kernel(const float* __restrict__ log_dt,
                 const float* __restrict__ log_A_real,
                 const float* __restrict__ A_imag,
                 const float* __restrict__ VinvB_real,
                 const float* __restrict__ VinvB_imag,
                 const float* __restrict__ CV_real,
                 const float* __restrict__ CV_imag,
                 float* __restrict__ out,
                 int L)
{
    __shared__ cfloat sAb[NSTATE];
    __shared__ cfloat sCoeff[NSTATE];
    __shared__ cfloat sP[NSTATE][7];   // A_bar^(4*2^k), k=0..6
    __shared__ cfloat sW[NSTATE];      // A_bar^512

    const int h   = blockIdx.x;
    const int tid = threadIdx.x;

    // ---- setup crew: 32 lanes, (n = lane/8, j = lane%8) ----
    if (tid < 32) {
        const int n = tid >> 3;
        const int j = tid & 7;
        const int idx = h * NSTATE + n;
        const float dt  = expf(log_dt[h]);
        const float Are = -expf(log_A_real[idx]);
        const float Aim = A_imag[idx];
        const float a = Are * dt;
        const float b = Aim * dt;

        if (j < 7) {
            sP[n][j] = cexp_scaled(a, b, (float)(LPT << j));
        } else {
            sW[n] = cexp_scaled(a, b, (float)STRIDE);
        }
        if (j == 0) {
            cfloat Ab = cexp_scaled(a, b, 1.0f);
            // B_bar = (A_bar - 1) * B / A
            const float Br = VinvB_real[idx], Bi = VinvB_imag[idx];
            const float t1r = (Ab.r - 1.0f) * Br - Ab.i * Bi;
            const float t1i = (Ab.r - 1.0f) * Bi + Ab.i * Br;
            const float invA = 1.0f / (Are * Are + Aim * Aim);
            const float Bbr = (t1r * Are + t1i * Aim) * invA;
            const float Bbi = (t1i * Are - t1r * Aim) * invA;
            // coeff = C * B_bar
            const float Cr = CV_real[idx], Ci = CV_imag[idx];
            cfloat cf;
            cf.r = Cr * Bbr - Ci * Bbi;
            cf.i = Cr * Bbi + Ci * Bbr;
            sAb[n]    = Ab;
            sCoeff[n] = cf;
        }
    }
    __syncthreads();

    // ---- per-thread seed composition (FMA pipe only) ----
    cfloat z[NSTATE][LPT];
    cfloat w[NSTATE];

#pragma unroll
    for (int n = 0; n < NSTATE; ++n) {
        cfloat E; E.r = 1.0f; E.i = 0.0f;
#pragma unroll
        for (int k = 0; k < 7; ++k) {
            cfloat P = sP[n][k];               // uniform smem broadcast
            if (!((tid >> k) & 1)) { P.r = 1.0f; P.i = 0.0f; }
            E = cmul(E, P);
        }
        const cfloat Ab = sAb[n];
        z[n][0] = cmul(sCoeff[n], E);          // coeff * A_bar^(4*tid)
#pragma unroll
        for (int jj = 1; jj < LPT; ++jj)
            z[n][jj] = cmul(z[n][jj - 1], Ab);
        w[n] = sW[n];
    }

    // ---- main loop ----
    float* rowp = out + (size_t)h * (size_t)L;

    for (int l = LPT * tid; l < L; l += STRIDE) {
        float4 v;
        v.x = (z[0][0].r + z[1][0].r) + (z[2][0].r + z[3][0].r);
        v.y = (z[0][1].r + z[1][1].r) + (z[2][1].r + z[3][1].r);
        v.z = (z[0][2].r + z[1][2].r) + (z[2][2].r + z[3][2].r);
        v.w = (z[0][3].r + z[1][3].r) + (z[2][3].r + z[3][3].r);
        if (l + LPT <= L) {
            *reinterpret_cast<float4*>(rowp + l) = v;
        } else {
            const float vv[4] = {v.x, v.y, v.z, v.w};
            for (int q = 0; q < 4 && l + q < L; ++q) rowp[l + q] = vv[q];
        }
#pragma unroll
        for (int n = 0; n < NSTATE; ++n) {
#pragma unroll
            for (int jj = 0; jj < LPT; ++jj)
                z[n][jj] = cmul(z[n][jj], w[n]);
        }
    }
}

extern "C" void kernel_launch(void* const* d_in, const int* in_sizes, int n_in,
                              void* d_out, int out_size)
{
    const float* log_dt     = (const float*)d_in[0];
    const float* log_A_real = (const float*)d_in[1];
    const float* A_imag     = (const float*)d_in[2];
    const float* VinvB_real = (const float*)d_in[3];
    const float* VinvB_imag = (const float*)d_in[4];
    const float* CV_real    = (const float*)d_in[5];
    const float* CV_imag    = (const float*)d_in[6];

    const int H = in_sizes[0];
    const int L = out_size / H;

    float* out = (float*)d_out;

    pmsn_kernel<<<H, TPB>>>(log_dt, log_A_real, A_imag,
                            VinvB_real, VinvB_imag,
                            CV_real, CV_imag, out, L);
}